// round 1
// baseline (speedup 1.0000x reference)
#include <cuda_runtime.h>
#include <math.h>
#include <stdint.h>

// ---------------- problem constants ----------------
#define B_TOK 4096
#define DIN   512
#define PP    1024
#define HH    2048
#define EE    8
#define HSH   4096
#define OUTN  29
#define CAP   4096   // max tokens per expert (top-k indices are distinct -> <= B)

// ---------------- scratch (device globals; no allocation APIs) ----------------
__device__ float g_p   [B_TOK * PP];          // projected input        [4096,1024]
__device__ float g_h   [EE * CAP * HH];       // expert fc1 out         [32768,2048]
__device__ float g_eo  [EE * CAP * PP];       // expert fc2 out         [32768,1024]
__device__ float g_moe [B_TOK * PP];          // combined MoE out
__device__ float g_sg  [B_TOK * HSH];         // silu(p@sg_w+b)
__device__ float g_su  [B_TOK * HSH];         // gate*up
__device__ float g_comb[B_TOK * PP];          // moe + shared
__device__ float g_hid1[B_TOK * HH];
__device__ float g_hid2[B_TOK * HH];
__device__ int   g_counts[EE];
__device__ int   g_slot_token[EE * CAP];
__device__ int   g_pair_slot [B_TOK * 2];
__device__ float g_pair_gate [B_TOK * 2];

__device__ __forceinline__ float silu_f(float x) { return x / (1.0f + expf(-x)); }

// ---------------- dense SGEMM: C = epi(A[M,K] @ B[K,N] + bias[N]) ----------------
// MODE: 0 = +bias ; 1 = silu(+bias) ; 2 = (+bias)*D ; 3 = (+bias)+D
#define BM 128
#define BN 128
#define BKD 8
#define TM 8
#define TN 8

template<int MODE>
__global__ __launch_bounds__(256)
void sgemm_k(const float* __restrict__ A, const float* __restrict__ Bm,
             const float* __restrict__ bias, const float* __restrict__ D,
             float* __restrict__ C, int M, int N, int K)
{
    __shared__ float As[BKD][BM];
    __shared__ float Bs[BKD][BN];
    const int tid  = threadIdx.x;
    const int row0 = blockIdx.y * BM;
    const int col0 = blockIdx.x * BN;
    const int tM = tid >> 4;    // 0..15
    const int tN = tid & 15;    // 0..15

    const int aRow  = tid >> 1;
    const int aCol4 = (tid & 1) * 4;
    const int bRow  = tid >> 5;
    const int bCol4 = (tid & 31) * 4;

    const float* Aptr = A + (size_t)(row0 + aRow) * K + aCol4;
    const float* Bptr = Bm + (size_t)bRow * N + col0 + bCol4;

    float acc[TM][TN];
#pragma unroll
    for (int i = 0; i < TM; i++)
#pragma unroll
        for (int j = 0; j < TN; j++) acc[i][j] = 0.f;

    for (int k0 = 0; k0 < K; k0 += BKD) {
        float4 av = *(const float4*)Aptr;
        As[aCol4 + 0][aRow] = av.x; As[aCol4 + 1][aRow] = av.y;
        As[aCol4 + 2][aRow] = av.z; As[aCol4 + 3][aRow] = av.w;
        *(float4*)&Bs[bRow][bCol4] = *(const float4*)Bptr;
        __syncthreads();
#pragma unroll
        for (int kk = 0; kk < BKD; kk++) {
            float ra[TM], rb[TN];
#pragma unroll
            for (int i = 0; i < TM; i++) ra[i] = As[kk][tM * TM + i];
#pragma unroll
            for (int j = 0; j < TN; j++) rb[j] = Bs[kk][tN * TN + j];
#pragma unroll
            for (int i = 0; i < TM; i++)
#pragma unroll
                for (int j = 0; j < TN; j++) acc[i][j] += ra[i] * rb[j];
        }
        __syncthreads();
        Aptr += BKD;
        Bptr += (size_t)BKD * N;
    }

#pragma unroll
    for (int i = 0; i < TM; i++) {
        int r = row0 + tM * TM + i;
#pragma unroll
        for (int j = 0; j < TN; j++) {
            int c = col0 + tN * TN + j;
            float v = acc[i][j] + bias[c];
            if (MODE == 1) v = silu_f(v);
            if (MODE == 2) v = v * D[(size_t)r * N + c];
            if (MODE == 3) v = v + D[(size_t)r * N + c];
            C[(size_t)r * N + c] = v;
        }
    }
}

// ---------------- grouped GEMM over padded per-expert segments ----------------
// GATHER=true : A row i = Abase[slot_token[e*CAP+m0+i]]  (stage 1, K=PP)
// GATHER=false: A row i = Abase[e*CAP+m0+i]              (stage 2, K=HH)
template<int MODE, bool GATHER>
__global__ __launch_bounds__(256)
void ggemm_k(const float* __restrict__ Abase, const float* __restrict__ Wbase,
             const float* __restrict__ biasBase, float* __restrict__ Cbase,
             const int* __restrict__ counts, const int* __restrict__ slot_token,
             int N, int K)
{
    const int e   = blockIdx.z;
    const int cnt = counts[e];
    const int m0  = blockIdx.y * BM;
    if (m0 >= cnt) return;

    __shared__ float As[BKD][BM];
    __shared__ float Bs[BKD][BN];
    const int tid  = threadIdx.x;
    const int col0 = blockIdx.x * BN;
    const int tM = tid >> 4;
    const int tN = tid & 15;

    const float* Bm   = Wbase + (size_t)e * K * N;
    const float* bias = biasBase + (size_t)e * N;
    float*       C    = Cbase + (size_t)e * CAP * N;

    const int aRow  = tid >> 1;
    const int aCol4 = (tid & 1) * 4;
    const int bRow  = tid >> 5;
    const int bCol4 = (tid & 31) * 4;

    const float* Aptr;
    if (GATHER) {
        int tok = slot_token[e * CAP + m0 + aRow]; // stale beyond cnt -> still in [0,B), masked at store
        Aptr = Abase + (size_t)tok * K + aCol4;
    } else {
        Aptr = Abase + (size_t)(e * CAP + m0 + aRow) * K + aCol4;
    }
    const float* Bptr = Bm + (size_t)bRow * N + col0 + bCol4;

    float acc[TM][TN];
#pragma unroll
    for (int i = 0; i < TM; i++)
#pragma unroll
        for (int j = 0; j < TN; j++) acc[i][j] = 0.f;

    for (int k0 = 0; k0 < K; k0 += BKD) {
        float4 av = *(const float4*)Aptr;
        As[aCol4 + 0][aRow] = av.x; As[aCol4 + 1][aRow] = av.y;
        As[aCol4 + 2][aRow] = av.z; As[aCol4 + 3][aRow] = av.w;
        *(float4*)&Bs[bRow][bCol4] = *(const float4*)Bptr;
        __syncthreads();
#pragma unroll
        for (int kk = 0; kk < BKD; kk++) {
            float ra[TM], rb[TN];
#pragma unroll
            for (int i = 0; i < TM; i++) ra[i] = As[kk][tM * TM + i];
#pragma unroll
            for (int j = 0; j < TN; j++) rb[j] = Bs[kk][tN * TN + j];
#pragma unroll
            for (int i = 0; i < TM; i++)
#pragma unroll
                for (int j = 0; j < TN; j++) acc[i][j] += ra[i] * rb[j];
        }
        __syncthreads();
        Aptr += BKD;
        Bptr += (size_t)BKD * N;
    }

#pragma unroll
    for (int i = 0; i < TM; i++) {
        int r = m0 + tM * TM + i;
        if (r < cnt) {
#pragma unroll
            for (int j = 0; j < TN; j++) {
                int c = col0 + tN * TN + j;
                float v = acc[i][j] + bias[c];
                if (MODE == 1) v = silu_f(v);
                C[(size_t)r * N + c] = v;
            }
        }
    }
}

// ---------------- router: logits = p@Wg, top-2, renormalized softmax gates ----------------
__global__ void zero_counts_k(int* counts)
{
    if (threadIdx.x < EE) counts[threadIdx.x] = 0;
}

__global__ void router_k(const float* __restrict__ p, const float* __restrict__ Wg,
                         int* __restrict__ counts, int* __restrict__ slot_token,
                         int* __restrict__ pair_slot, float* __restrict__ pair_gate)
{
    const int t = blockIdx.x;
    const int tid = threadIdx.x; // 128 threads
    __shared__ float red[EE][128];
    float acc[EE];
#pragma unroll
    for (int e = 0; e < EE; e++) acc[e] = 0.f;
    const float* pr = p + (size_t)t * PP;
    for (int j = tid; j < PP; j += 128) {
        float pv = pr[j];
        const float* wg = Wg + (size_t)j * EE;
#pragma unroll
        for (int e = 0; e < EE; e++) acc[e] += pv * wg[e];
    }
#pragma unroll
    for (int e = 0; e < EE; e++) red[e][tid] = acc[e];
    __syncthreads();
    if (tid == 0) {
        float logit[EE];
        for (int e = 0; e < EE; e++) {
            float s = 0.f;
            for (int i = 0; i < 128; i++) s += red[e][i];
            logit[e] = s;
        }
        int i0 = 0;
        for (int e = 1; e < EE; e++) if (logit[e] > logit[i0]) i0 = e;
        int i1 = (i0 == 0) ? 1 : 0;
        for (int e = 0; e < EE; e++) {
            if (e == i0) continue;
            if (logit[e] > logit[i1]) i1 = e;
        }
        // gates = softmax over {l0, l1} (== normalized top-2 of full softmax)
        float g0 = 1.f / (1.f + expf(logit[i1] - logit[i0]));
        float g1 = 1.f - g0;
        int s0 = atomicAdd(&counts[i0], 1);
        int s1 = atomicAdd(&counts[i1], 1);
        slot_token[i0 * CAP + s0] = t;
        slot_token[i1 * CAP + s1] = t;
        pair_slot[2 * t]     = i0 * CAP + s0;
        pair_slot[2 * t + 1] = i1 * CAP + s1;
        pair_gate[2 * t]     = g0;
        pair_gate[2 * t + 1] = g1;
    }
}

// ---------------- combine: moe[t,:] = g0*eo[s0,:] + g1*eo[s1,:] ----------------
__global__ void combine_k(const float* __restrict__ eo, const int* __restrict__ pair_slot,
                          const float* __restrict__ pair_gate, float* __restrict__ moe)
{
    int idx = blockIdx.x * blockDim.x + threadIdx.x;
    if (idx >= B_TOK * PP) return;
    int t = idx >> 10;      // / PP
    int j = idx & (PP - 1); // % PP
    int s0 = pair_slot[2 * t], s1 = pair_slot[2 * t + 1];
    float g0 = pair_gate[2 * t], g1 = pair_gate[2 * t + 1];
    moe[idx] = g0 * eo[(size_t)s0 * PP + j] + g1 * eo[(size_t)s1 * PP + j];
}

// ---------------- head: out[t,o] = hid2[t,:] @ head_w[:,o] + head_b[o] ----------------
__global__ __launch_bounds__(256)
void head_k(const float* __restrict__ hid2, const float* __restrict__ head_w,
            const float* __restrict__ head_b, float* __restrict__ out)
{
    const int t = blockIdx.x;
    const int tid = threadIdx.x;
    const int lane = tid & 31;
    const int warp = tid >> 5; // 0..7
    __shared__ float row[HH];
    for (int i = tid; i < HH; i += 256) row[i] = hid2[(size_t)t * HH + i];
    __syncthreads();
#pragma unroll
    for (int oo = 0; oo < 4; oo++) {
        int o = warp + oo * 8;
        if (o >= OUTN) break;
        float s = 0.f;
        for (int i = lane; i < HH; i += 32) s += row[i] * head_w[(size_t)i * OUTN + o];
#pragma unroll
        for (int off = 16; off > 0; off >>= 1) s += __shfl_down_sync(0xFFFFFFFFu, s, off);
        if (lane == 0) out[(size_t)t * OUTN + o] = s + head_b[o];
    }
}

// ---------------- launch ----------------
template <typename T>
static T* symaddr(const void* sym)
{
    void* p = nullptr;
    cudaGetSymbolAddress(&p, sym);
    return (T*)p;
}

extern "C" void kernel_launch(void* const* d_in, const int* in_sizes, int n_in,
                              void* d_out, int out_size)
{
    const float* x      = (const float*)d_in[0];
    const float* Wproj  = (const float*)d_in[1];
    const float* bproj  = (const float*)d_in[2];
    const float* Wg     = (const float*)d_in[3];
    const float* W1     = (const float*)d_in[4];
    const float* b1     = (const float*)d_in[5];
    const float* W2     = (const float*)d_in[6];
    const float* b2     = (const float*)d_in[7];
    const float* sg_w   = (const float*)d_in[8];
    const float* sg_b   = (const float*)d_in[9];
    const float* su_w   = (const float*)d_in[10];
    const float* su_b   = (const float*)d_in[11];
    const float* sd_w   = (const float*)d_in[12];
    const float* sd_b   = (const float*)d_in[13];
    const float* m1_w   = (const float*)d_in[14];
    const float* m1_b   = (const float*)d_in[15];
    const float* m2_w   = (const float*)d_in[16];
    const float* m2_b   = (const float*)d_in[17];
    const float* head_w = (const float*)d_in[18];
    const float* head_b = (const float*)d_in[19];
    float* out = (float*)d_out;

    float* p_buf   = symaddr<float>(g_p);
    float* h_buf   = symaddr<float>(g_h);
    float* eo_buf  = symaddr<float>(g_eo);
    float* moe_buf = symaddr<float>(g_moe);
    float* sg_buf  = symaddr<float>(g_sg);
    float* su_buf  = symaddr<float>(g_su);
    float* cb_buf  = symaddr<float>(g_comb);
    float* h1_buf  = symaddr<float>(g_hid1);
    float* h2_buf  = symaddr<float>(g_hid2);
    int*   counts  = symaddr<int>(g_counts);
    int*   stok    = symaddr<int>(g_slot_token);
    int*   pslot   = symaddr<int>(g_pair_slot);
    float* pgate   = symaddr<float>(g_pair_gate);

    // 1. p = x @ Wproj + bproj                       [4096,1024] K=512
    sgemm_k<0><<<dim3(PP / BN, B_TOK / BM), 256>>>(x, Wproj, bproj, nullptr, p_buf,
                                                   B_TOK, PP, DIN);
    // 2. router: top-2 gating, scatter to per-expert slot lists
    zero_counts_k<<<1, 32>>>(counts);
    router_k<<<B_TOK, 128>>>(p_buf, Wg, counts, stok, pslot, pgate);
    // 3. expert fc1: h = silu(p_gathered @ W1[e] + b1[e])   N=2048 K=1024
    ggemm_k<1, true><<<dim3(HH / BN, CAP / BM, EE), 256>>>(p_buf, W1, b1, h_buf,
                                                           counts, stok, HH, PP);
    // 4. expert fc2: eo = h @ W2[e] + b2[e]                 N=1024 K=2048
    ggemm_k<0, false><<<dim3(PP / BN, CAP / BM, EE), 256>>>(h_buf, W2, b2, eo_buf,
                                                            counts, stok, PP, HH);
    // 5. weighted combine
    combine_k<<<(B_TOK * PP + 255) / 256, 256>>>(eo_buf, pslot, pgate, moe_buf);
    // 6. shared expert SwiGLU
    sgemm_k<1><<<dim3(HSH / BN, B_TOK / BM), 256>>>(p_buf, sg_w, sg_b, nullptr, sg_buf,
                                                    B_TOK, HSH, PP);
    sgemm_k<2><<<dim3(HSH / BN, B_TOK / BM), 256>>>(p_buf, su_w, su_b, sg_buf, su_buf,
                                                    B_TOK, HSH, PP);
    // 7. down proj + residual MoE add: comb = su @ sd_w + sd_b + moe
    sgemm_k<3><<<dim3(PP / BN, B_TOK / BM), 256>>>(su_buf, sd_w, sd_b, moe_buf, cb_buf,
                                                   B_TOK, PP, HSH);
    // 8. output MLP
    sgemm_k<1><<<dim3(HH / BN, B_TOK / BM), 256>>>(cb_buf, m1_w, m1_b, nullptr, h1_buf,
                                                   B_TOK, HH, PP);
    sgemm_k<0><<<dim3(HH / BN, B_TOK / BM), 256>>>(h1_buf, m2_w, m2_b, nullptr, h2_buf,
                                                   B_TOK, HH, HH);
    // 9. head
    head_k<<<B_TOK, 256>>>(h2_buf, head_w, head_b, out);
}